// round 14
// baseline (speedup 1.0000x reference)
#include <cuda_runtime.h>
#include <cuda_bf16.h>
#include <cstdint>

// ============================================================================
// SimplifiedTopologyExtractor — algebraic reduction:
//   out = ReLU(LayerNorm(emb[:, :, :256] @ W_enc + b_enc))
// (pooled == embeddings exactly; proj/cdist/topk is dead code.)
//
// fp32 GEMM via bf16 hi/lo split on mma.sync m16n8k16:
//   a*b ≈ ah*bh + ah*bl + al*bh   (err ~2^-18 rel).
// Round 14 = R12 champion, de-phased:
//   (1) A converted to smem ONCE up front in the proven conflict-free
//       48B-stride layout (R10's upfront-A used a conflicted 32B layout),
//   (2) NO __syncthreads in the mainloop: B WAR via empty mbarriers
//       (count-16), warps skew up to 2 chunks so LDSM overlaps MMA,
//   (3) inner loop identical to R12 (R13's 3-buffer ring reverted).
// ============================================================================

#define THREADS 512
#define MTILE 64
#define KD 256
#define KCH 32
#define NCHUNK (KD / KCH)      // 8
#define B_CHUNK 65536          // [part 2][kr 32][1024B], XOR-unit swizzled

// smem layout (bytes)
#define OFF_A     0                      // 16 ks-blocks x 6144 (h 3072 | l 3072)
#define A_TOTAL   98304
#define OFF_MBAR  A_TOTAL                // full0,full1,empty0,empty1 (4 x 8B)
#define OFF_B     (A_TOTAL + 1024)       // 2 stages x 65536
#define SMEM_TOTAL (OFF_B + 2 * B_CHUNK) // 230400 (<= 232448 cap)
// epilogue scratch reuses the A region (after post-mainloop syncthreads)
#define OFF_PS    0                      // [64 rows][8 nw]
#define OFF_PQ    2048
#define OFF_MZ    4096

// prepped B (bf16 hi/lo): [chunk 8][part 2][kr 32][unit 64], unit^=(kr&7)
__device__ __align__(128) unsigned char g_Bpre[8 * B_CHUNK];   // 512 KB

__device__ __forceinline__ uint32_t smem_u32(const void* p) {
    uint32_t a;
    asm("{ .reg .u64 t; cvta.to.shared.u64 t, %1; cvt.u32.u64 %0, t; }"
        : "=r"(a) : "l"(p));
    return a;
}

__device__ __forceinline__ void ldsm4(uint32_t* r, uint32_t addr) {
    asm volatile("ldmatrix.sync.aligned.m8n8.x4.shared.b16 {%0,%1,%2,%3}, [%4];"
                 : "=r"(r[0]), "=r"(r[1]), "=r"(r[2]), "=r"(r[3]) : "r"(addr));
}
__device__ __forceinline__ void ldsm4t(uint32_t* r, uint32_t addr) {
    asm volatile("ldmatrix.sync.aligned.m8n8.x4.trans.shared.b16 {%0,%1,%2,%3}, [%4];"
                 : "=r"(r[0]), "=r"(r[1]), "=r"(r[2]), "=r"(r[3]) : "r"(addr));
}

__device__ __forceinline__ void mma16816(float* d, const uint32_t* a,
                                         uint32_t b0, uint32_t b1) {
    asm volatile(
        "mma.sync.aligned.m16n8k16.row.col.f32.bf16.bf16.f32 "
        "{%0,%1,%2,%3}, {%4,%5,%6,%7}, {%8,%9}, {%0,%1,%2,%3};"
        : "+f"(d[0]), "+f"(d[1]), "+f"(d[2]), "+f"(d[3])
        : "r"(a[0]), "r"(a[1]), "r"(a[2]), "r"(a[3]), "r"(b0), "r"(b1));
}

#define MBAR_INIT(addr, cnt) \
    asm volatile("mbarrier.init.shared.b64 [%0], %1;" :: "r"(addr), "r"(cnt) : "memory")

#define MBAR_ARRIVE(addr) \
    asm volatile("mbarrier.arrive.shared.b64 _, [%0];" :: "r"(addr) : "memory")

#define MBAR_EXPECT_TX(addr, bytes) \
    asm volatile("mbarrier.arrive.expect_tx.shared.b64 _, [%0], %1;" \
                 :: "r"(addr), "r"((uint32_t)(bytes)) : "memory")

#define MBAR_WAIT(addr, par) do {                                              \
    uint32_t _m = (addr), _p = (uint32_t)(par), _done;                         \
    asm volatile("{\n\t.reg .pred p;\n\t"                                      \
        "mbarrier.try_wait.parity.acquire.cta.shared::cta.b64 p, [%1], %2;\n\t"\
        "selp.b32 %0, 1, 0, p;\n\t}" : "=r"(_done) : "r"(_m), "r"(_p) : "memory"); \
    if (!_done) {                                                              \
        asm volatile("{\n\t.reg .pred P1;\n\t"                                 \
            "W%=:\n\t"                                                         \
            "mbarrier.try_wait.parity.acquire.cta.shared::cta.b64 P1, [%0], %1, 0x989680;\n\t" \
            "@P1 bra.uni D%=;\n\t"                                             \
            "bra.uni W%=;\n\t"                                                 \
            "D%=:\n\t}" :: "r"(_m), "r"(_p) : "memory");                       \
    }                                                                          \
} while (0)

__device__ __forceinline__ void bulk_copy(uint32_t dst, const void* src,
                                          uint32_t bytes, uint32_t mbar) {
    asm volatile(
        "cp.async.bulk.shared::cluster.global.mbarrier::complete_tx::bytes "
        "[%0], [%1], %2, [%3];"
        :: "r"(dst), "l"(src), "r"(bytes), "r"(mbar) : "memory");
}

__device__ __forceinline__ void split_f4(float4 v, uint32_t& h01, uint32_t& h23,
                                         uint32_t& l01, uint32_t& l23) {
    float f[4] = {v.x, v.y, v.z, v.w};
    unsigned short hs[4], ls[4];
#pragma unroll
    for (int i = 0; i < 4; i++) {
        __nv_bfloat16 h = __float2bfloat16(f[i]);
        float rem = f[i] - __bfloat162float(h);
        __nv_bfloat16 l = __float2bfloat16(rem);
        hs[i] = __bfloat16_as_ushort(h);
        ls[i] = __bfloat16_as_ushort(l);
    }
    h01 = (uint32_t)hs[0] | ((uint32_t)hs[1] << 16);
    h23 = (uint32_t)hs[2] | ((uint32_t)hs[3] << 16);
    l01 = (uint32_t)ls[0] | ((uint32_t)ls[1] << 16);
    l23 = (uint32_t)ls[2] | ((uint32_t)ls[3] << 16);
}

// ---- prep B: W_enc[256,512] -> hi/lo bf16, chunk-tiled + XOR swizzle ----
__global__ void prep_b_kernel(const float* __restrict__ W) {
    int t = blockIdx.x * 256 + threadIdx.x;   // 256 k x 128 nq
    int k  = t >> 7;
    int nq = t & 127;
    float4 v = *(const float4*)(W + (size_t)k * 512 + nq * 4);
    uint32_t h01, h23, l01, l23;
    split_f4(v, h01, h23, l01, l23);
    int c = k >> 5, kr = k & 31;
    int unit = nq >> 1;
    int sw   = unit ^ (kr & 7);
    size_t base = (size_t)c * B_CHUNK + (size_t)kr * 1024
                + (size_t)sw * 16 + (nq & 1) * 8;
    *(uint2*)(g_Bpre + base)         = make_uint2(h01, h23);
    *(uint2*)(g_Bpre + base + 32768) = make_uint2(l01, l23);
}

// ---- GEMM + fused bias/LayerNorm/ReLU ----
__global__ void __launch_bounds__(THREADS, 1)
gemm_ln_kernel(const float* __restrict__ emb,
               const float* __restrict__ bias,
               const float* __restrict__ gamma,
               const float* __restrict__ beta,
               float* __restrict__ out)
{
    extern __shared__ __align__(1024) unsigned char smem[];
    const uint32_t sb = smem_u32(smem);
    const int tid = threadIdx.x;
    const int wid = tid >> 5;
    const int lane = tid & 31;
    const int mw = wid >> 3;       // 2 m-warps: rows mw*32..+32
    const int nw = wid & 7;        // 8 n-warps: cols nw*64..+64
    const int m0 = blockIdx.x * MTILE;

    float acc[2][8][4];            // [mt][j*2+nn][frag]
#pragma unroll
    for (int mt = 0; mt < 2; mt++)
#pragma unroll
        for (int ng = 0; ng < 8; ng++)
#pragma unroll
            for (int e = 0; e < 4; e++) acc[mt][ng][e] = 0.0f;

    // mbarriers: full[s] (tx-based, count 1), empty[s] (count 16, 1/warp)
    if (tid == 0) {
        MBAR_INIT(sb + OFF_MBAR + 0, 1);    // full0
        MBAR_INIT(sb + OFF_MBAR + 8, 1);    // full1
        MBAR_INIT(sb + OFF_MBAR + 16, 16);  // empty0
        MBAR_INIT(sb + OFF_MBAR + 24, 16);  // empty1
    }
    __syncthreads();

    // kick off B chunks 0,1 (first use of both stages — no empty wait)
    if (tid == 0) {
        MBAR_EXPECT_TX(sb + OFF_MBAR + 0, B_CHUNK);
        bulk_copy(sb + OFF_B, g_Bpre, B_CHUNK, sb + OFF_MBAR + 0);
        MBAR_EXPECT_TX(sb + OFF_MBAR + 8, B_CHUNK);
        bulk_copy(sb + OFF_B + B_CHUNK, g_Bpre + B_CHUNK, B_CHUNK,
                  sb + OFF_MBAR + 8);
    }

    // ---- A: convert ALL of K=256 to smem once (conflict-free 48B layout) ----
    // layout: [ks 16]{ h: rows 64 x 48B | l: +3072 }, quad kk at +kk*8
    {
        const int arow = tid >> 3;
        const int qb   = tid & 7;
        const float* ap = emb + (size_t)(m0 + arow) * 512;
#pragma unroll
        for (int i = 0; i < 8; i++) {
            const int quad  = qb + i * 8;        // 0..63
            const int kglob = quad * 4;
            float4 v = *(const float4*)(ap + kglob);
            uint32_t h01, h23, l01, l23;
            split_f4(v, h01, h23, l01, l23);
            const uint32_t base = (uint32_t)(quad >> 2) * 6144
                                + (uint32_t)arow * 48 + (uint32_t)(quad & 3) * 8;
            *(uint2*)(smem + OFF_A + base)        = make_uint2(h01, h23);
            *(uint2*)(smem + OFF_A + base + 3072) = make_uint2(l01, l23);
        }
    }
    __syncthreads();   // A visible; mainloop below has NO CTA-wide barrier

    // lane addressing
    const uint32_t lrow = lane & 15, lchk = lane >> 4;
    const uint32_t aLane = ((uint32_t)mw * 32 + lrow) * 48 + lchk * 16;
    const uint32_t bRow = lrow * 1024;
    const uint32_t swz  = lrow & 7;
    const uint32_t uBase = (uint32_t)nw * 8 + lchk;   // 8 units = 64 cols/warp

#pragma unroll 1
    for (int c = 0; c < NCHUNK; ++c) {
        const int s = c & 1;
        MBAR_WAIT(sb + OFF_MBAR + s * 8, (c >> 1) & 1);   // B(c) landed

        const uint32_t stB = sb + OFF_B + (uint32_t)s * B_CHUNK;

#pragma unroll
        for (int ks = 0; ks < 2; ks++) {
            const uint32_t aBlk = sb + OFF_A
                                + (uint32_t)(c * 2 + ks) * 6144 + aLane;
            // A fragments: m32 = 2 x m16
            uint32_t Ah[2][4], Al[2][4];
#pragma unroll
            for (int mt = 0; mt < 2; mt++) {
                const uint32_t aAd = aBlk + (uint32_t)mt * 768;
                ldsm4(Ah[mt], aAd);
                ldsm4(Al[mt], aAd + 3072);
            }

            const uint32_t bH = stB + (uint32_t)ks * 16384 + bRow;
            // register double-buffered B fragments (R12 structure)
            uint32_t Bh[2][4], Bl[2][4];
            {
                const uint32_t a0 = bH + ((uBase ^ swz) << 4);
                ldsm4t(Bh[0], a0);
                ldsm4t(Bl[0], a0 + 32768);
            }
#pragma unroll
            for (int j = 0; j < 4; j++) {
                const int cu = j & 1, nx = cu ^ 1;
                if (j < 3) {
                    const uint32_t u = uBase + (uint32_t)(j + 1) * 2;
                    const uint32_t ad = bH + ((u ^ swz) << 4);
                    ldsm4t(Bh[nx], ad);
                    ldsm4t(Bl[nx], ad + 32768);
                }
#pragma unroll
                for (int mt = 0; mt < 2; mt++) {
#pragma unroll
                    for (int nn = 0; nn < 2; nn++) {
                        float* d = acc[mt][j * 2 + nn];
                        mma16816(d, Ah[mt], Bh[cu][nn * 2], Bh[cu][nn * 2 + 1]);
                        mma16816(d, Ah[mt], Bl[cu][nn * 2], Bl[cu][nn * 2 + 1]);
                        mma16816(d, Al[mt], Bh[cu][nn * 2], Bh[cu][nn * 2 + 1]);
                    }
                }
            }
        }

        // this warp is done reading B stage s (MMAs depend on the LDSMs)
        if (lane == 0) MBAR_ARRIVE(sb + OFF_MBAR + 16 + s * 8);

        // producer: refill stage s with chunk c+2 after chunk c fully consumed
        if (tid == 0 && c + 2 < NCHUNK) {
            MBAR_WAIT(sb + OFF_MBAR + 16 + s * 8, (c >> 1) & 1);
            MBAR_EXPECT_TX(sb + OFF_MBAR + s * 8, B_CHUNK);
            bulk_copy(stB, g_Bpre + (size_t)(c + 2) * B_CHUNK, B_CHUNK,
                      sb + OFF_MBAR + s * 8);
        }
    }

    __syncthreads();   // all warps out of the mainloop; A region reusable

    // ======== fused epilogue: +bias, LayerNorm(512), *gamma+beta, ReLU ========
    const int g = lane >> 2, t4 = lane & 3;
    float* ps = (float*)(smem + OFF_PS);      // [64 rows][8 nw]
    float* pq = (float*)(smem + OFF_PQ);
    float2* mz = (float2*)(smem + OFF_MZ);    // [64] {mu, rstd}

    float sA[4] = {0.f, 0.f, 0.f, 0.f}, qA[4] = {0.f, 0.f, 0.f, 0.f};
#pragma unroll
    for (int mt = 0; mt < 2; mt++) {
#pragma unroll
        for (int ng = 0; ng < 8; ng++) {
            const int col = nw * 64 + ng * 8 + t4 * 2;
            const float2 bv = *(const float2*)(bias + col);
            acc[mt][ng][0] += bv.x; acc[mt][ng][1] += bv.y;
            acc[mt][ng][2] += bv.x; acc[mt][ng][3] += bv.y;
            sA[mt * 2 + 0] += acc[mt][ng][0] + acc[mt][ng][1];
            qA[mt * 2 + 0] += acc[mt][ng][0] * acc[mt][ng][0]
                            + acc[mt][ng][1] * acc[mt][ng][1];
            sA[mt * 2 + 1] += acc[mt][ng][2] + acc[mt][ng][3];
            qA[mt * 2 + 1] += acc[mt][ng][2] * acc[mt][ng][2]
                            + acc[mt][ng][3] * acc[mt][ng][3];
        }
    }
#pragma unroll
    for (int r4 = 0; r4 < 4; r4++) {
        sA[r4] += __shfl_xor_sync(0xffffffffu, sA[r4], 1);
        qA[r4] += __shfl_xor_sync(0xffffffffu, qA[r4], 1);
        sA[r4] += __shfl_xor_sync(0xffffffffu, sA[r4], 2);
        qA[r4] += __shfl_xor_sync(0xffffffffu, qA[r4], 2);
    }
    if (t4 == 0) {
#pragma unroll
        for (int r4 = 0; r4 < 4; r4++) {
            const int row = mw * 32 + (r4 >> 1) * 16 + (r4 & 1) * 8 + g;
            ps[row * 8 + nw] = sA[r4];
            pq[row * 8 + nw] = qA[r4];
        }
    }
    __syncthreads();
    if (tid < 64) {
        float ss = 0.f, qq = 0.f;
#pragma unroll
        for (int w = 0; w < 8; w++) { ss += ps[tid * 8 + w]; qq += pq[tid * 8 + w]; }
        const float mu  = ss * (1.0f / 512.0f);
        const float var = qq * (1.0f / 512.0f) - mu * mu;
        mz[tid] = make_float2(mu, rsqrtf(var + 1e-5f));
    }
    __syncthreads();

#pragma unroll
    for (int mt = 0; mt < 2; mt++) {
#pragma unroll
        for (int h = 0; h < 2; h++) {
            const int row = mw * 32 + mt * 16 + h * 8 + g;
            const float2 m = mz[row];
#pragma unroll
            for (int ng = 0; ng < 8; ng++) {
                const int col = nw * 64 + ng * 8 + t4 * 2;
                const float2 gv = *(const float2*)(gamma + col);
                const float2 tv = *(const float2*)(beta + col);
                const float v0 = acc[mt][ng][h * 2 + 0];
                const float v1 = acc[mt][ng][h * 2 + 1];
                const float o0 = fmaxf((v0 - m.x) * m.y * gv.x + tv.x, 0.0f);
                const float o1 = fmaxf((v1 - m.x) * m.y * gv.y + tv.y, 0.0f);
                *(float2*)(out + (size_t)(m0 + row) * 512 + col) = make_float2(o0, o1);
            }
        }
    }
}

extern "C" void kernel_launch(void* const* d_in, const int* in_sizes, int n_in,
                              void* d_out, int out_size)
{
    // metadata order: embeddings, W_proj, b_proj, W_enc, b_enc, ln_gamma, ln_beta
    const float* emb   = (const float*)d_in[0];
    const float* W_enc = (const float*)d_in[3];
    const float* b_enc = (const float*)d_in[4];
    const float* gam   = (const float*)d_in[5];
    const float* bet   = (const float*)d_in[6];
    float* out = (float*)d_out;

    prep_b_kernel<<<128, 256>>>(W_enc);

    cudaFuncSetAttribute(gemm_ln_kernel,
                         cudaFuncAttributeMaxDynamicSharedMemorySize, SMEM_TOTAL);
    gemm_ln_kernel<<<16384 / MTILE, THREADS, SMEM_TOTAL>>>(emb, b_enc, gam, bet, out);
}

// round 15
// speedup vs baseline: 1.2653x; 1.2653x over previous
#include <cuda_runtime.h>
#include <cuda_fp16.h>
#include <cstdint>

// ============================================================================
// SimplifiedTopologyExtractor — algebraic reduction:
//   out = ReLU(LayerNorm(emb[:, :, :256] @ W_enc + b_enc))
// (pooled == embeddings exactly; proj/cdist/topk is dead code.)
//
// Round 15: fp16 TWO-TERM split GEMM on mma.sync m16n8k16 (f32 accum):
//   a = ah + al (fp16 hi/lo, residual 2^-22), b ~= bh (fp16, residual 2^-12)
//   d = ah*bh + al*bh = a*bh   -> rel err ~2^-12 ~ 2.4e-4 (< 1e-3 gate)
// vs R12's bf16 3-term: 33% fewer MMAs (tensor floor 21->14us) and B smem
// traffic halved (hi part only). Skeleton identical to the R12 champion.
// ============================================================================

#define THREADS 512
#define MTILE 64
#define KD 256
#define KCH 32
#define NCHUNK (KD / KCH)      // 8
#define B_CHUNK 32768          // [kr 32][1024B fp16 row], XOR-unit swizzled

// A stage: [ks 2][part 2][64 rows x 48B]
#define A_STAGE 12288
// smem layout (bytes)
#define OFF_A     0                          // 2 stages x 12288
#define OFF_B     24576                      // 2 stages x 32768
#define OFF_MBAR  (OFF_B + 2 * B_CHUNK)      // 90112
#define OFF_PS    (OFF_MBAR + 64)            // [64 rows][8 nw]
#define OFF_PQ    (OFF_PS + 2048)
#define OFF_MZ    (OFF_PQ + 2048)
#define SMEM_TOTAL (OFF_MZ + 512)            // 94784

// prepped B (fp16 hi only): [chunk 8][kr 32][unit 64], unit^=(kr&7)
__device__ __align__(128) unsigned char g_Bpre[8 * B_CHUNK];   // 256 KB

__device__ __forceinline__ uint32_t smem_u32(const void* p) {
    uint32_t a;
    asm("{ .reg .u64 t; cvta.to.shared.u64 t, %1; cvt.u32.u64 %0, t; }"
        : "=r"(a) : "l"(p));
    return a;
}

__device__ __forceinline__ void ldsm4(uint32_t* r, uint32_t addr) {
    asm volatile("ldmatrix.sync.aligned.m8n8.x4.shared.b16 {%0,%1,%2,%3}, [%4];"
                 : "=r"(r[0]), "=r"(r[1]), "=r"(r[2]), "=r"(r[3]) : "r"(addr));
}
__device__ __forceinline__ void ldsm4t(uint32_t* r, uint32_t addr) {
    asm volatile("ldmatrix.sync.aligned.m8n8.x4.trans.shared.b16 {%0,%1,%2,%3}, [%4];"
                 : "=r"(r[0]), "=r"(r[1]), "=r"(r[2]), "=r"(r[3]) : "r"(addr));
}

__device__ __forceinline__ void mma16816(float* d, const uint32_t* a,
                                         uint32_t b0, uint32_t b1) {
    asm volatile(
        "mma.sync.aligned.m16n8k16.row.col.f32.f16.f16.f32 "
        "{%0,%1,%2,%3}, {%4,%5,%6,%7}, {%8,%9}, {%0,%1,%2,%3};"
        : "+f"(d[0]), "+f"(d[1]), "+f"(d[2]), "+f"(d[3])
        : "r"(a[0]), "r"(a[1]), "r"(a[2]), "r"(a[3]), "r"(b0), "r"(b1));
}

#define MBAR_INIT(addr, cnt) \
    asm volatile("mbarrier.init.shared.b64 [%0], %1;" :: "r"(addr), "r"(cnt) : "memory")

#define MBAR_EXPECT_TX(addr, bytes) \
    asm volatile("mbarrier.arrive.expect_tx.shared.b64 _, [%0], %1;" \
                 :: "r"(addr), "r"((uint32_t)(bytes)) : "memory")

#define MBAR_WAIT(addr, par) do {                                              \
    uint32_t _m = (addr), _p = (uint32_t)(par), _done;                         \
    asm volatile("{\n\t.reg .pred p;\n\t"                                      \
        "mbarrier.try_wait.parity.acquire.cta.shared::cta.b64 p, [%1], %2;\n\t"\
        "selp.b32 %0, 1, 0, p;\n\t}" : "=r"(_done) : "r"(_m), "r"(_p) : "memory"); \
    if (!_done) {                                                              \
        asm volatile("{\n\t.reg .pred P1;\n\t"                                 \
            "W%=:\n\t"                                                         \
            "mbarrier.try_wait.parity.acquire.cta.shared::cta.b64 P1, [%0], %1, 0x989680;\n\t" \
            "@P1 bra.uni D%=;\n\t"                                             \
            "bra.uni W%=;\n\t"                                                 \
            "D%=:\n\t}" :: "r"(_m), "r"(_p) : "memory");                       \
    }                                                                          \
} while (0)

__device__ __forceinline__ void bulk_copy(uint32_t dst, const void* src,
                                          uint32_t bytes, uint32_t mbar) {
    asm volatile(
        "cp.async.bulk.shared::cluster.global.mbarrier::complete_tx::bytes "
        "[%0], [%1], %2, [%3];"
        :: "r"(dst), "l"(src), "r"(bytes), "r"(mbar) : "memory");
}

// fp16 hi/lo split of float4 -> packed half2 pairs
__device__ __forceinline__ void split_f4_h(float4 v, uint32_t& h01, uint32_t& h23,
                                           uint32_t& l01, uint32_t& l23) {
    float f[4] = {v.x, v.y, v.z, v.w};
    unsigned short hs[4], ls[4];
#pragma unroll
    for (int i = 0; i < 4; i++) {
        __half h = __float2half_rn(f[i]);
        float rem = f[i] - __half2float(h);
        __half l = __float2half_rn(rem);
        hs[i] = __half_as_ushort(h);
        ls[i] = __half_as_ushort(l);
    }
    h01 = (uint32_t)hs[0] | ((uint32_t)hs[1] << 16);
    h23 = (uint32_t)hs[2] | ((uint32_t)hs[3] << 16);
    l01 = (uint32_t)ls[0] | ((uint32_t)ls[1] << 16);
    l23 = (uint32_t)ls[2] | ((uint32_t)ls[3] << 16);
}

// ---- prep B: W_enc[256,512] -> fp16 (hi only), chunk-tiled + XOR swizzle ----
__global__ void prep_b_kernel(const float* __restrict__ W) {
    int t = blockIdx.x * 256 + threadIdx.x;   // 256 k x 128 nq
    int k  = t >> 7;
    int nq = t & 127;
    float4 v = *(const float4*)(W + (size_t)k * 512 + nq * 4);
    unsigned short hs[4];
    float f[4] = {v.x, v.y, v.z, v.w};
#pragma unroll
    for (int i = 0; i < 4; i++)
        hs[i] = __half_as_ushort(__float2half_rn(f[i]));
    uint2 hp = make_uint2((uint32_t)hs[0] | ((uint32_t)hs[1] << 16),
                          (uint32_t)hs[2] | ((uint32_t)hs[3] << 16));
    int c = k >> 5, kr = k & 31;
    int unit = nq >> 1;
    int sw   = unit ^ (kr & 7);
    size_t base = (size_t)c * B_CHUNK + (size_t)kr * 1024
                + (size_t)sw * 16 + (nq & 1) * 8;
    *(uint2*)(g_Bpre + base) = hp;
}

// ---- GEMM + fused bias/LayerNorm/ReLU ----
__global__ void __launch_bounds__(THREADS, 1)
gemm_ln_kernel(const float* __restrict__ emb,
               const float* __restrict__ bias,
               const float* __restrict__ gamma,
               const float* __restrict__ beta,
               float* __restrict__ out)
{
    extern __shared__ __align__(1024) unsigned char smem[];
    const uint32_t sb = smem_u32(smem);
    const int tid = threadIdx.x;
    const int wid = tid >> 5;
    const int lane = tid & 31;
    const int mw = wid >> 3;       // 2 m-warps: rows mw*32..+32
    const int nw = wid & 7;        // 8 n-warps: cols nw*64..+64
    const int m0 = blockIdx.x * MTILE;

    float acc[2][8][4];            // [mt][j*2+nn][frag]
#pragma unroll
    for (int mt = 0; mt < 2; mt++)
#pragma unroll
        for (int ng = 0; ng < 8; ng++)
#pragma unroll
            for (int e = 0; e < 4; e++) acc[mt][ng][e] = 0.0f;

    if (tid == 0) {
        MBAR_INIT(sb + OFF_MBAR + 0, 1);
        MBAR_INIT(sb + OFF_MBAR + 8, 1);
    }
    __syncthreads();

    // A staging: thread owns one float4 (4 k) of the 64x32 chunk
    const int a_row = tid >> 3;
    const int a_kq  = tid & 7;
    const int a_ks  = a_kq >> 2;
    const int a_kk  = a_kq & 3;
    const float* a_src = emb + (size_t)(m0 + a_row) * 512 + a_kq * 4;
    const uint32_t a_off = (uint32_t)a_ks * 6144
                         + (uint32_t)a_row * 48 + (uint32_t)a_kk * 8;

#define STS_A(stg, v) do {                                                      \
    uint32_t _h01, _h23, _l01, _l23;                                            \
    split_f4_h((v), _h01, _h23, _l01, _l23);                                    \
    const uint32_t _b = (uint32_t)(stg) * A_STAGE + a_off;                      \
    *(uint2*)(smem + OFF_A + _b)        = make_uint2(_h01, _h23);               \
    *(uint2*)(smem + OFF_A + _b + 3072) = make_uint2(_l01, _l23);               \
} while (0)

    // ---- prologue: stage 0 ----
    {
        float4 a0 = *(const float4*)(a_src);
        STS_A(0, a0);
    }
    if (tid == 0) {
        MBAR_EXPECT_TX(sb + OFF_MBAR + 0, B_CHUNK);
        bulk_copy(sb + OFF_B, g_Bpre, B_CHUNK, sb + OFF_MBAR + 0);
    }
    float4 aR = *(const float4*)(a_src + 32);

    // lane addressing
    const uint32_t lrow = lane & 15, lchk = lane >> 4;
    const uint32_t aLane = ((uint32_t)mw * 32 + lrow) * 48 + lchk * 16;
    const uint32_t bRow = lrow * 1024;
    const uint32_t swz  = lrow & 7;
    const uint32_t uBase = (uint32_t)nw * 8 + lchk;   // 8 units = 64 cols/warp

#pragma unroll 1
    for (int c = 0; c < NCHUNK; ++c) {
        const int s = c & 1;
        MBAR_WAIT(sb + OFF_MBAR + s * 8, (c >> 1) & 1);   // B(c) landed
        __syncthreads();   // A(c) visible; stage s^1 fully consumed

        if (c + 1 < NCHUNK) {
            STS_A(s ^ 1, aR);
            if (tid == 0) {
                MBAR_EXPECT_TX(sb + OFF_MBAR + (s ^ 1) * 8, B_CHUNK);
                bulk_copy(sb + OFF_B + (uint32_t)(s ^ 1) * B_CHUNK,
                          g_Bpre + (size_t)(c + 1) * B_CHUNK, B_CHUNK,
                          sb + OFF_MBAR + (s ^ 1) * 8);
            }
        }
        if (c + 2 < NCHUNK) aR = *(const float4*)(a_src + (c + 2) * 32);

        const uint32_t stA = sb + OFF_A + (uint32_t)s * A_STAGE;
        const uint32_t stB = sb + OFF_B + (uint32_t)s * B_CHUNK;

#pragma unroll
        for (int ks = 0; ks < 2; ks++) {
            // A fragments: m32 = 2 x m16, hi + lo parts
            uint32_t Ah[2][4], Al[2][4];
#pragma unroll
            for (int mt = 0; mt < 2; mt++) {
                const uint32_t aAd = stA + (uint32_t)ks * 6144 + aLane
                                   + (uint32_t)mt * 768;
                ldsm4(Ah[mt], aAd);
                ldsm4(Al[mt], aAd + 3072);
            }

            const uint32_t bH = stB + (uint32_t)ks * 16384 + bRow;
            // register double-buffered B fragments (hi only)
            uint32_t Bh[2][4];
            ldsm4t(Bh[0], bH + ((uBase ^ swz) << 4));
#pragma unroll
            for (int j = 0; j < 4; j++) {
                const int cu = j & 1, nx = cu ^ 1;
                if (j < 3) {
                    const uint32_t u = uBase + (uint32_t)(j + 1) * 2;
                    ldsm4t(Bh[nx], bH + ((u ^ swz) << 4));
                }
#pragma unroll
                for (int mt = 0; mt < 2; mt++) {
#pragma unroll
                    for (int nn = 0; nn < 2; nn++) {
                        float* d = acc[mt][j * 2 + nn];
                        mma16816(d, Ah[mt], Bh[cu][nn * 2], Bh[cu][nn * 2 + 1]);
                        mma16816(d, Al[mt], Bh[cu][nn * 2], Bh[cu][nn * 2 + 1]);
                    }
                }
            }
        }
    }

    // ======== fused epilogue: +bias, LayerNorm(512), *gamma+beta, ReLU ========
    const int g = lane >> 2, t4 = lane & 3;
    float* ps = (float*)(smem + OFF_PS);      // [64 rows][8 nw]
    float* pq = (float*)(smem + OFF_PQ);
    float2* mz = (float2*)(smem + OFF_MZ);    // [64] {mu, rstd}

    float sA[4] = {0.f, 0.f, 0.f, 0.f}, qA[4] = {0.f, 0.f, 0.f, 0.f};
#pragma unroll
    for (int mt = 0; mt < 2; mt++) {
#pragma unroll
        for (int ng = 0; ng < 8; ng++) {
            const int col = nw * 64 + ng * 8 + t4 * 2;
            const float2 bv = *(const float2*)(bias + col);
            acc[mt][ng][0] += bv.x; acc[mt][ng][1] += bv.y;
            acc[mt][ng][2] += bv.x; acc[mt][ng][3] += bv.y;
            sA[mt * 2 + 0] += acc[mt][ng][0] + acc[mt][ng][1];
            qA[mt * 2 + 0] += acc[mt][ng][0] * acc[mt][ng][0]
                            + acc[mt][ng][1] * acc[mt][ng][1];
            sA[mt * 2 + 1] += acc[mt][ng][2] + acc[mt][ng][3];
            qA[mt * 2 + 1] += acc[mt][ng][2] * acc[mt][ng][2]
                            + acc[mt][ng][3] * acc[mt][ng][3];
        }
    }
#pragma unroll
    for (int r4 = 0; r4 < 4; r4++) {
        sA[r4] += __shfl_xor_sync(0xffffffffu, sA[r4], 1);
        qA[r4] += __shfl_xor_sync(0xffffffffu, qA[r4], 1);
        sA[r4] += __shfl_xor_sync(0xffffffffu, sA[r4], 2);
        qA[r4] += __shfl_xor_sync(0xffffffffu, qA[r4], 2);
    }
    if (t4 == 0) {
#pragma unroll
        for (int r4 = 0; r4 < 4; r4++) {
            const int row = mw * 32 + (r4 >> 1) * 16 + (r4 & 1) * 8 + g;
            ps[row * 8 + nw] = sA[r4];
            pq[row * 8 + nw] = qA[r4];
        }
    }
    __syncthreads();
    if (tid < 64) {
        float ss = 0.f, qq = 0.f;
#pragma unroll
        for (int w = 0; w < 8; w++) { ss += ps[tid * 8 + w]; qq += pq[tid * 8 + w]; }
        const float mu  = ss * (1.0f / 512.0f);
        const float var = qq * (1.0f / 512.0f) - mu * mu;
        mz[tid] = make_float2(mu, rsqrtf(var + 1e-5f));
    }
    __syncthreads();

#pragma unroll
    for (int mt = 0; mt < 2; mt++) {
#pragma unroll
        for (int h = 0; h < 2; h++) {
            const int row = mw * 32 + mt * 16 + h * 8 + g;
            const float2 m = mz[row];
#pragma unroll
            for (int ng = 0; ng < 8; ng++) {
                const int col = nw * 64 + ng * 8 + t4 * 2;
                const float2 gv = *(const float2*)(gamma + col);
                const float2 tv = *(const float2*)(beta + col);
                const float v0 = acc[mt][ng][h * 2 + 0];
                const float v1 = acc[mt][ng][h * 2 + 1];
                const float o0 = fmaxf((v0 - m.x) * m.y * gv.x + tv.x, 0.0f);
                const float o1 = fmaxf((v1 - m.x) * m.y * gv.y + tv.y, 0.0f);
                *(float2*)(out + (size_t)(m0 + row) * 512 + col) = make_float2(o0, o1);
            }
        }
    }
}

extern "C" void kernel_launch(void* const* d_in, const int* in_sizes, int n_in,
                              void* d_out, int out_size)
{
    // metadata order: embeddings, W_proj, b_proj, W_enc, b_enc, ln_gamma, ln_beta
    const float* emb   = (const float*)d_in[0];
    const float* W_enc = (const float*)d_in[3];
    const float* b_enc = (const float*)d_in[4];
    const float* gam   = (const float*)d_in[5];
    const float* bet   = (const float*)d_in[6];
    float* out = (float*)d_out;

    prep_b_kernel<<<128, 256>>>(W_enc);

    cudaFuncSetAttribute(gemm_ln_kernel,
                         cudaFuncAttributeMaxDynamicSharedMemorySize, SMEM_TOTAL);
    gemm_ln_kernel<<<16384 / MTILE, THREADS, SMEM_TOTAL>>>(emb, b_enc, gam, bet, out);
}

// round 16
// speedup vs baseline: 1.6570x; 1.3096x over previous
#include <cuda_runtime.h>
#include <cuda_fp16.h>
#include <cstdint>

// ============================================================================
// SimplifiedTopologyExtractor — algebraic reduction:
//   out = ReLU(LayerNorm(emb[:, :, :256] @ W_enc + b_enc))
// (pooled == embeddings exactly; proj/cdist/topk is dead code.)
//
// Round 16: PLAIN fp16 GEMM (single term) on mma.sync m16n8k16, f32 accum.
//   a ~= fp16(a), b ~= fp16(b): independent RN roundings, random-sign
//   K=256 sum -> expected rel err ~ sqrt(2) x (measured 2.08e-4 for B-only)
//   ~ 2.9e-4 < 1e-3 gate. Halves MMAs vs R15 (tensor floor 13.9 -> 7us)
//   and halves A smem/convert. Skeleton = R15/R12 champion unchanged.
// ============================================================================

#define THREADS 512
#define MTILE 64
#define KD 256
#define KCH 32
#define NCHUNK (KD / KCH)      // 8
#define B_CHUNK 32768          // [kr 32][1024B fp16 row], XOR-unit swizzled

// A stage: [ks 2][64 rows x 48B]  (fp16 hi only)
#define A_STAGE 6144
// smem layout (bytes)
#define OFF_A     0                          // 2 stages x 6144
#define OFF_B     12288                      // 2 stages x 32768
#define OFF_MBAR  (OFF_B + 2 * B_CHUNK)      // 77824
#define OFF_PS    (OFF_MBAR + 64)            // [64 rows][8 nw]
#define OFF_PQ    (OFF_PS + 2048)
#define OFF_MZ    (OFF_PQ + 2048)
#define SMEM_TOTAL (OFF_MZ + 512)            // 82496

// prepped B (fp16): [chunk 8][kr 32][unit 64], unit^=(kr&7)
__device__ __align__(128) unsigned char g_Bpre[8 * B_CHUNK];   // 256 KB

__device__ __forceinline__ uint32_t smem_u32(const void* p) {
    uint32_t a;
    asm("{ .reg .u64 t; cvta.to.shared.u64 t, %1; cvt.u32.u64 %0, t; }"
        : "=r"(a) : "l"(p));
    return a;
}

__device__ __forceinline__ void ldsm4(uint32_t* r, uint32_t addr) {
    asm volatile("ldmatrix.sync.aligned.m8n8.x4.shared.b16 {%0,%1,%2,%3}, [%4];"
                 : "=r"(r[0]), "=r"(r[1]), "=r"(r[2]), "=r"(r[3]) : "r"(addr));
}
__device__ __forceinline__ void ldsm4t(uint32_t* r, uint32_t addr) {
    asm volatile("ldmatrix.sync.aligned.m8n8.x4.trans.shared.b16 {%0,%1,%2,%3}, [%4];"
                 : "=r"(r[0]), "=r"(r[1]), "=r"(r[2]), "=r"(r[3]) : "r"(addr));
}

__device__ __forceinline__ void mma16816(float* d, const uint32_t* a,
                                         uint32_t b0, uint32_t b1) {
    asm volatile(
        "mma.sync.aligned.m16n8k16.row.col.f32.f16.f16.f32 "
        "{%0,%1,%2,%3}, {%4,%5,%6,%7}, {%8,%9}, {%0,%1,%2,%3};"
        : "+f"(d[0]), "+f"(d[1]), "+f"(d[2]), "+f"(d[3])
        : "r"(a[0]), "r"(a[1]), "r"(a[2]), "r"(a[3]), "r"(b0), "r"(b1));
}

#define MBAR_INIT(addr, cnt) \
    asm volatile("mbarrier.init.shared.b64 [%0], %1;" :: "r"(addr), "r"(cnt) : "memory")

#define MBAR_EXPECT_TX(addr, bytes) \
    asm volatile("mbarrier.arrive.expect_tx.shared.b64 _, [%0], %1;" \
                 :: "r"(addr), "r"((uint32_t)(bytes)) : "memory")

#define MBAR_WAIT(addr, par) do {                                              \
    uint32_t _m = (addr), _p = (uint32_t)(par), _done;                         \
    asm volatile("{\n\t.reg .pred p;\n\t"                                      \
        "mbarrier.try_wait.parity.acquire.cta.shared::cta.b64 p, [%1], %2;\n\t"\
        "selp.b32 %0, 1, 0, p;\n\t}" : "=r"(_done) : "r"(_m), "r"(_p) : "memory"); \
    if (!_done) {                                                              \
        asm volatile("{\n\t.reg .pred P1;\n\t"                                 \
            "W%=:\n\t"                                                         \
            "mbarrier.try_wait.parity.acquire.cta.shared::cta.b64 P1, [%0], %1, 0x989680;\n\t" \
            "@P1 bra.uni D%=;\n\t"                                             \
            "bra.uni W%=;\n\t"                                                 \
            "D%=:\n\t}" :: "r"(_m), "r"(_p) : "memory");                       \
    }                                                                          \
} while (0)

__device__ __forceinline__ void bulk_copy(uint32_t dst, const void* src,
                                          uint32_t bytes, uint32_t mbar) {
    asm volatile(
        "cp.async.bulk.shared::cluster.global.mbarrier::complete_tx::bytes "
        "[%0], [%1], %2, [%3];"
        :: "r"(dst), "l"(src), "r"(bytes), "r"(mbar) : "memory");
}

// ---- prep B: W_enc[256,512] -> fp16, chunk-tiled + XOR swizzle ----
__global__ void prep_b_kernel(const float* __restrict__ W) {
    int t = blockIdx.x * 256 + threadIdx.x;   // 256 k x 128 nq
    int k  = t >> 7;
    int nq = t & 127;
    float4 v = *(const float4*)(W + (size_t)k * 512 + nq * 4);
    unsigned short hs[4];
    float f[4] = {v.x, v.y, v.z, v.w};
#pragma unroll
    for (int i = 0; i < 4; i++)
        hs[i] = __half_as_ushort(__float2half_rn(f[i]));
    uint2 hp = make_uint2((uint32_t)hs[0] | ((uint32_t)hs[1] << 16),
                          (uint32_t)hs[2] | ((uint32_t)hs[3] << 16));
    int c = k >> 5, kr = k & 31;
    int unit = nq >> 1;
    int sw   = unit ^ (kr & 7);
    size_t base = (size_t)c * B_CHUNK + (size_t)kr * 1024
                + (size_t)sw * 16 + (nq & 1) * 8;
    *(uint2*)(g_Bpre + base) = hp;
}

// ---- GEMM + fused bias/LayerNorm/ReLU ----
__global__ void __launch_bounds__(THREADS, 1)
gemm_ln_kernel(const float* __restrict__ emb,
               const float* __restrict__ bias,
               const float* __restrict__ gamma,
               const float* __restrict__ beta,
               float* __restrict__ out)
{
    extern __shared__ __align__(1024) unsigned char smem[];
    const uint32_t sb = smem_u32(smem);
    const int tid = threadIdx.x;
    const int wid = tid >> 5;
    const int lane = tid & 31;
    const int mw = wid >> 3;       // 2 m-warps: rows mw*32..+32
    const int nw = wid & 7;        // 8 n-warps: cols nw*64..+64
    const int m0 = blockIdx.x * MTILE;

    float acc[2][8][4];            // [mt][j*2+nn][frag]
#pragma unroll
    for (int mt = 0; mt < 2; mt++)
#pragma unroll
        for (int ng = 0; ng < 8; ng++)
#pragma unroll
            for (int e = 0; e < 4; e++) acc[mt][ng][e] = 0.0f;

    if (tid == 0) {
        MBAR_INIT(sb + OFF_MBAR + 0, 1);
        MBAR_INIT(sb + OFF_MBAR + 8, 1);
    }
    __syncthreads();

    // A staging: thread owns one float4 (4 k) of the 64x32 chunk
    const int a_row = tid >> 3;
    const int a_kq  = tid & 7;
    const int a_ks  = a_kq >> 2;
    const int a_kk  = a_kq & 3;
    const float* a_src = emb + (size_t)(m0 + a_row) * 512 + a_kq * 4;
    const uint32_t a_off = (uint32_t)a_ks * 3072
                         + (uint32_t)a_row * 48 + (uint32_t)a_kk * 8;

#define STS_A(stg, v) do {                                                      \
    unsigned short _hs0 = __half_as_ushort(__float2half_rn((v).x));             \
    unsigned short _hs1 = __half_as_ushort(__float2half_rn((v).y));             \
    unsigned short _hs2 = __half_as_ushort(__float2half_rn((v).z));             \
    unsigned short _hs3 = __half_as_ushort(__float2half_rn((v).w));             \
    uint32_t _h01 = (uint32_t)_hs0 | ((uint32_t)_hs1 << 16);                    \
    uint32_t _h23 = (uint32_t)_hs2 | ((uint32_t)_hs3 << 16);                    \
    *(uint2*)(smem + OFF_A + (uint32_t)(stg) * A_STAGE + a_off) =               \
        make_uint2(_h01, _h23);                                                 \
} while (0)

    // ---- prologue: stage 0 ----
    {
        float4 a0 = *(const float4*)(a_src);
        STS_A(0, a0);
    }
    if (tid == 0) {
        MBAR_EXPECT_TX(sb + OFF_MBAR + 0, B_CHUNK);
        bulk_copy(sb + OFF_B, g_Bpre, B_CHUNK, sb + OFF_MBAR + 0);
    }
    float4 aR = *(const float4*)(a_src + 32);

    // lane addressing
    const uint32_t lrow = lane & 15, lchk = lane >> 4;
    const uint32_t aLane = ((uint32_t)mw * 32 + lrow) * 48 + lchk * 16;
    const uint32_t bRow = lrow * 1024;
    const uint32_t swz  = lrow & 7;
    const uint32_t uBase = (uint32_t)nw * 8 + lchk;   // 8 units = 64 cols/warp

#pragma unroll 1
    for (int c = 0; c < NCHUNK; ++c) {
        const int s = c & 1;
        MBAR_WAIT(sb + OFF_MBAR + s * 8, (c >> 1) & 1);   // B(c) landed
        __syncthreads();   // A(c) visible; stage s^1 fully consumed

        if (c + 1 < NCHUNK) {
            STS_A(s ^ 1, aR);
            if (tid == 0) {
                MBAR_EXPECT_TX(sb + OFF_MBAR + (s ^ 1) * 8, B_CHUNK);
                bulk_copy(sb + OFF_B + (uint32_t)(s ^ 1) * B_CHUNK,
                          g_Bpre + (size_t)(c + 1) * B_CHUNK, B_CHUNK,
                          sb + OFF_MBAR + (s ^ 1) * 8);
            }
        }
        if (c + 2 < NCHUNK) aR = *(const float4*)(a_src + (c + 2) * 32);

        const uint32_t stA = sb + OFF_A + (uint32_t)s * A_STAGE;
        const uint32_t stB = sb + OFF_B + (uint32_t)s * B_CHUNK;

#pragma unroll
        for (int ks = 0; ks < 2; ks++) {
            // A fragments: m32 = 2 x m16 (fp16, single term)
            uint32_t Ah[2][4];
#pragma unroll
            for (int mt = 0; mt < 2; mt++)
                ldsm4(Ah[mt], stA + (uint32_t)ks * 3072 + aLane
                              + (uint32_t)mt * 768);

            const uint32_t bH = stB + (uint32_t)ks * 16384 + bRow;
            // register double-buffered B fragments
            uint32_t Bh[2][4];
            ldsm4t(Bh[0], bH + ((uBase ^ swz) << 4));
#pragma unroll
            for (int j = 0; j < 4; j++) {
                const int cu = j & 1, nx = cu ^ 1;
                if (j < 3) {
                    const uint32_t u = uBase + (uint32_t)(j + 1) * 2;
                    ldsm4t(Bh[nx], bH + ((u ^ swz) << 4));
                }
#pragma unroll
                for (int mt = 0; mt < 2; mt++) {
#pragma unroll
                    for (int nn = 0; nn < 2; nn++) {
                        float* d = acc[mt][j * 2 + nn];
                        mma16816(d, Ah[mt], Bh[cu][nn * 2], Bh[cu][nn * 2 + 1]);
                    }
                }
            }
        }
    }

    // ======== fused epilogue: +bias, LayerNorm(512), *gamma+beta, ReLU ========
    const int g = lane >> 2, t4 = lane & 3;
    float* ps = (float*)(smem + OFF_PS);      // [64 rows][8 nw]
    float* pq = (float*)(smem + OFF_PQ);
    float2* mz = (float2*)(smem + OFF_MZ);    // [64] {mu, rstd}

    float sA[4] = {0.f, 0.f, 0.f, 0.f}, qA[4] = {0.f, 0.f, 0.f, 0.f};
#pragma unroll
    for (int mt = 0; mt < 2; mt++) {
#pragma unroll
        for (int ng = 0; ng < 8; ng++) {
            const int col = nw * 64 + ng * 8 + t4 * 2;
            const float2 bv = *(const float2*)(bias + col);
            acc[mt][ng][0] += bv.x; acc[mt][ng][1] += bv.y;
            acc[mt][ng][2] += bv.x; acc[mt][ng][3] += bv.y;
            sA[mt * 2 + 0] += acc[mt][ng][0] + acc[mt][ng][1];
            qA[mt * 2 + 0] += acc[mt][ng][0] * acc[mt][ng][0]
                            + acc[mt][ng][1] * acc[mt][ng][1];
            sA[mt * 2 + 1] += acc[mt][ng][2] + acc[mt][ng][3];
            qA[mt * 2 + 1] += acc[mt][ng][2] * acc[mt][ng][2]
                            + acc[mt][ng][3] * acc[mt][ng][3];
        }
    }
#pragma unroll
    for (int r4 = 0; r4 < 4; r4++) {
        sA[r4] += __shfl_xor_sync(0xffffffffu, sA[r4], 1);
        qA[r4] += __shfl_xor_sync(0xffffffffu, qA[r4], 1);
        sA[r4] += __shfl_xor_sync(0xffffffffu, sA[r4], 2);
        qA[r4] += __shfl_xor_sync(0xffffffffu, qA[r4], 2);
    }
    if (t4 == 0) {
#pragma unroll
        for (int r4 = 0; r4 < 4; r4++) {
            const int row = mw * 32 + (r4 >> 1) * 16 + (r4 & 1) * 8 + g;
            ps[row * 8 + nw] = sA[r4];
            pq[row * 8 + nw] = qA[r4];
        }
    }
    __syncthreads();
    if (tid < 64) {
        float ss = 0.f, qq = 0.f;
#pragma unroll
        for (int w = 0; w < 8; w++) { ss += ps[tid * 8 + w]; qq += pq[tid * 8 + w]; }
        const float mu  = ss * (1.0f / 512.0f);
        const float var = qq * (1.0f / 512.0f) - mu * mu;
        mz[tid] = make_float2(mu, rsqrtf(var + 1e-5f));
    }
    __syncthreads();

#pragma unroll
    for (int mt = 0; mt < 2; mt++) {
#pragma unroll
        for (int h = 0; h < 2; h++) {
            const int row = mw * 32 + mt * 16 + h * 8 + g;
            const float2 m = mz[row];
#pragma unroll
            for (int ng = 0; ng < 8; ng++) {
                const int col = nw * 64 + ng * 8 + t4 * 2;
                const float2 gv = *(const float2*)(gamma + col);
                const float2 tv = *(const float2*)(beta + col);
                const float v0 = acc[mt][ng][h * 2 + 0];
                const float v1 = acc[mt][ng][h * 2 + 1];
                const float o0 = fmaxf((v0 - m.x) * m.y * gv.x + tv.x, 0.0f);
                const float o1 = fmaxf((v1 - m.x) * m.y * gv.y + tv.y, 0.0f);
                *(float2*)(out + (size_t)(m0 + row) * 512 + col) = make_float2(o0, o1);
            }
        }
    }
}

extern "C" void kernel_launch(void* const* d_in, const int* in_sizes, int n_in,
                              void* d_out, int out_size)
{
    // metadata order: embeddings, W_proj, b_proj, W_enc, b_enc, ln_gamma, ln_beta
    const float* emb   = (const float*)d_in[0];
    const float* W_enc = (const float*)d_in[3];
    const float* b_enc = (const float*)d_in[4];
    const float* gam   = (const float*)d_in[5];
    const float* bet   = (const float*)d_in[6];
    float* out = (float*)d_out;

    prep_b_kernel<<<128, 256>>>(W_enc);

    cudaFuncSetAttribute(gemm_ln_kernel,
                         cudaFuncAttributeMaxDynamicSharedMemorySize, SMEM_TOTAL);
    gemm_ln_kernel<<<16384 / MTILE, THREADS, SMEM_TOTAL>>>(emb, b_enc, gam, bet, out);
}

// round 17
// speedup vs baseline: 1.7757x; 1.0716x over previous
#include <cuda_runtime.h>
#include <cuda_fp16.h>
#include <cstdint>

// ============================================================================
// SimplifiedTopologyExtractor — algebraic reduction:
//   out = ReLU(LayerNorm(emb[:, :, :256] @ W_enc + b_enc))
// (pooled == embeddings exactly; proj/cdist/topk is dead code.)
//
// Round 17 = R16 champion (plain fp16 GEMM, rel_err 2.9e-4 < 1e-3) with
// KCH 32 -> 64: 4 chunk boundaries instead of 8. The ~2.7k cyc/chunk
// boundary cost (mbar wait + barrier convergence + pipeline refill) is
// now the dominant term over the 1k MMA issue floor; amortize it 2x.
// ============================================================================

#define THREADS 512
#define MTILE 64
#define KD 256
#define KCH 64
#define NCHUNK (KD / KCH)      // 4
#define B_CHUNK 65536          // [kr 64][1024B fp16 row], XOR-unit swizzled

// A stage: [ks 4][64 rows x 48B]  (fp16)
#define A_STAGE 12288
// smem layout (bytes)
#define OFF_A     0                          // 2 stages x 12288
#define OFF_B     24576                      // 2 stages x 65536
#define OFF_MBAR  (OFF_B + 2 * B_CHUNK)      // 155648
#define OFF_PS    (OFF_MBAR + 64)            // [64 rows][8 nw]
#define OFF_PQ    (OFF_PS + 2048)
#define OFF_MZ    (OFF_PQ + 2048)
#define SMEM_TOTAL (OFF_MZ + 512)            // 160320

// prepped B (fp16): [chunk 4][kr 64][unit 64], unit^=(kr&7)
__device__ __align__(128) unsigned char g_Bpre[4 * B_CHUNK];   // 256 KB

__device__ __forceinline__ uint32_t smem_u32(const void* p) {
    uint32_t a;
    asm("{ .reg .u64 t; cvta.to.shared.u64 t, %1; cvt.u32.u64 %0, t; }"
        : "=r"(a) : "l"(p));
    return a;
}

__device__ __forceinline__ void ldsm4(uint32_t* r, uint32_t addr) {
    asm volatile("ldmatrix.sync.aligned.m8n8.x4.shared.b16 {%0,%1,%2,%3}, [%4];"
                 : "=r"(r[0]), "=r"(r[1]), "=r"(r[2]), "=r"(r[3]) : "r"(addr));
}
__device__ __forceinline__ void ldsm4t(uint32_t* r, uint32_t addr) {
    asm volatile("ldmatrix.sync.aligned.m8n8.x4.trans.shared.b16 {%0,%1,%2,%3}, [%4];"
                 : "=r"(r[0]), "=r"(r[1]), "=r"(r[2]), "=r"(r[3]) : "r"(addr));
}

__device__ __forceinline__ void mma16816(float* d, const uint32_t* a,
                                         uint32_t b0, uint32_t b1) {
    asm volatile(
        "mma.sync.aligned.m16n8k16.row.col.f32.f16.f16.f32 "
        "{%0,%1,%2,%3}, {%4,%5,%6,%7}, {%8,%9}, {%0,%1,%2,%3};"
        : "+f"(d[0]), "+f"(d[1]), "+f"(d[2]), "+f"(d[3])
        : "r"(a[0]), "r"(a[1]), "r"(a[2]), "r"(a[3]), "r"(b0), "r"(b1));
}

#define MBAR_INIT(addr, cnt) \
    asm volatile("mbarrier.init.shared.b64 [%0], %1;" :: "r"(addr), "r"(cnt) : "memory")

#define MBAR_EXPECT_TX(addr, bytes) \
    asm volatile("mbarrier.arrive.expect_tx.shared.b64 _, [%0], %1;" \
                 :: "r"(addr), "r"((uint32_t)(bytes)) : "memory")

#define MBAR_WAIT(addr, par) do {                                              \
    uint32_t _m = (addr), _p = (uint32_t)(par), _done;                         \
    asm volatile("{\n\t.reg .pred p;\n\t"                                      \
        "mbarrier.try_wait.parity.acquire.cta.shared::cta.b64 p, [%1], %2;\n\t"\
        "selp.b32 %0, 1, 0, p;\n\t}" : "=r"(_done) : "r"(_m), "r"(_p) : "memory"); \
    if (!_done) {                                                              \
        asm volatile("{\n\t.reg .pred P1;\n\t"                                 \
            "W%=:\n\t"                                                         \
            "mbarrier.try_wait.parity.acquire.cta.shared::cta.b64 P1, [%0], %1, 0x989680;\n\t" \
            "@P1 bra.uni D%=;\n\t"                                             \
            "bra.uni W%=;\n\t"                                                 \
            "D%=:\n\t}" :: "r"(_m), "r"(_p) : "memory");                       \
    }                                                                          \
} while (0)

__device__ __forceinline__ void bulk_copy(uint32_t dst, const void* src,
                                          uint32_t bytes, uint32_t mbar) {
    asm volatile(
        "cp.async.bulk.shared::cluster.global.mbarrier::complete_tx::bytes "
        "[%0], [%1], %2, [%3];"
        :: "r"(dst), "l"(src), "r"(bytes), "r"(mbar) : "memory");
}

// ---- prep B: W_enc[256,512] -> fp16, chunk-tiled + XOR swizzle ----
__global__ void prep_b_kernel(const float* __restrict__ W) {
    int t = blockIdx.x * 256 + threadIdx.x;   // 256 k x 128 nq
    int k  = t >> 7;
    int nq = t & 127;
    float4 v = *(const float4*)(W + (size_t)k * 512 + nq * 4);
    unsigned short hs[4];
    float f[4] = {v.x, v.y, v.z, v.w};
#pragma unroll
    for (int i = 0; i < 4; i++)
        hs[i] = __half_as_ushort(__float2half_rn(f[i]));
    uint2 hp = make_uint2((uint32_t)hs[0] | ((uint32_t)hs[1] << 16),
                          (uint32_t)hs[2] | ((uint32_t)hs[3] << 16));
    int c = k >> 6, kr = k & 63;
    int unit = nq >> 1;
    int sw   = unit ^ (kr & 7);
    size_t base = (size_t)c * B_CHUNK + (size_t)kr * 1024
                + (size_t)sw * 16 + (nq & 1) * 8;
    *(uint2*)(g_Bpre + base) = hp;
}

// ---- GEMM + fused bias/LayerNorm/ReLU ----
__global__ void __launch_bounds__(THREADS, 1)
gemm_ln_kernel(const float* __restrict__ emb,
               const float* __restrict__ bias,
               const float* __restrict__ gamma,
               const float* __restrict__ beta,
               float* __restrict__ out)
{
    extern __shared__ __align__(1024) unsigned char smem[];
    const uint32_t sb = smem_u32(smem);
    const int tid = threadIdx.x;
    const int wid = tid >> 5;
    const int lane = tid & 31;
    const int mw = wid >> 3;       // 2 m-warps: rows mw*32..+32
    const int nw = wid & 7;        // 8 n-warps: cols nw*64..+64
    const int m0 = blockIdx.x * MTILE;

    float acc[2][8][4];            // [mt][j*2+nn][frag]
#pragma unroll
    for (int mt = 0; mt < 2; mt++)
#pragma unroll
        for (int ng = 0; ng < 8; ng++)
#pragma unroll
            for (int e = 0; e < 4; e++) acc[mt][ng][e] = 0.0f;

    if (tid == 0) {
        MBAR_INIT(sb + OFF_MBAR + 0, 1);
        MBAR_INIT(sb + OFF_MBAR + 8, 1);
    }
    __syncthreads();

    // A staging: thread owns TWO float4 (quads qd, qd+8) of the 64x64 chunk
    const int a_row = tid >> 3;
    const int a_q0  = tid & 7;            // quads a_q0 and a_q0+8 (of 16)
    const float* a_src = emb + (size_t)(m0 + a_row) * 512;

#define A_OFF(qd) ((uint32_t)((qd) >> 2) * 3072 \
                 + (uint32_t)a_row * 48 + (uint32_t)((qd) & 3) * 8)

#define STS_A1(stg, v, qd) do {                                                 \
    unsigned short _h0 = __half_as_ushort(__float2half_rn((v).x));              \
    unsigned short _h1 = __half_as_ushort(__float2half_rn((v).y));              \
    unsigned short _h2 = __half_as_ushort(__float2half_rn((v).z));              \
    unsigned short _h3 = __half_as_ushort(__float2half_rn((v).w));              \
    *(uint2*)(smem + OFF_A + (uint32_t)(stg) * A_STAGE + A_OFF(qd)) =           \
        make_uint2((uint32_t)_h0 | ((uint32_t)_h1 << 16),                       \
                   (uint32_t)_h2 | ((uint32_t)_h3 << 16));                      \
} while (0)

    // ---- prologue: stage 0 (chunk 0 = k[0..63]) ----
    {
        float4 v0 = *(const float4*)(a_src + a_q0 * 4);
        float4 v1 = *(const float4*)(a_src + (a_q0 + 8) * 4);
        STS_A1(0, v0, a_q0);
        STS_A1(0, v1, a_q0 + 8);
    }
    if (tid == 0) {
        MBAR_EXPECT_TX(sb + OFF_MBAR + 0, B_CHUNK);
        bulk_copy(sb + OFF_B, g_Bpre, B_CHUNK, sb + OFF_MBAR + 0);
    }
    float4 aR0 = *(const float4*)(a_src + 64 + a_q0 * 4);
    float4 aR1 = *(const float4*)(a_src + 64 + (a_q0 + 8) * 4);

    // lane addressing
    const uint32_t lrow = lane & 15, lchk = lane >> 4;
    const uint32_t aLane = ((uint32_t)mw * 32 + lrow) * 48 + lchk * 16;
    const uint32_t bRow = lrow * 1024;
    const uint32_t swz  = lrow & 7;
    const uint32_t uBase = (uint32_t)nw * 8 + lchk;   // 8 units = 64 cols/warp

#pragma unroll 1
    for (int c = 0; c < NCHUNK; ++c) {
        const int s = c & 1;
        MBAR_WAIT(sb + OFF_MBAR + s * 8, (c >> 1) & 1);   // B(c) landed
        __syncthreads();   // A(c) visible; stage s^1 fully consumed

        if (c + 1 < NCHUNK) {
            STS_A1(s ^ 1, aR0, a_q0);
            STS_A1(s ^ 1, aR1, a_q0 + 8);
            if (tid == 0) {
                MBAR_EXPECT_TX(sb + OFF_MBAR + (s ^ 1) * 8, B_CHUNK);
                bulk_copy(sb + OFF_B + (uint32_t)(s ^ 1) * B_CHUNK,
                          g_Bpre + (size_t)(c + 1) * B_CHUNK, B_CHUNK,
                          sb + OFF_MBAR + (s ^ 1) * 8);
            }
        }
        if (c + 2 < NCHUNK) {
            aR0 = *(const float4*)(a_src + (c + 2) * 64 + a_q0 * 4);
            aR1 = *(const float4*)(a_src + (c + 2) * 64 + (a_q0 + 8) * 4);
        }

        const uint32_t stA = sb + OFF_A + (uint32_t)s * A_STAGE;
        const uint32_t stB = sb + OFF_B + (uint32_t)s * B_CHUNK;

#pragma unroll
        for (int ks = 0; ks < 4; ks++) {
            // A fragments: m32 = 2 x m16 (fp16, single term)
            uint32_t Ah[2][4];
#pragma unroll
            for (int mt = 0; mt < 2; mt++)
                ldsm4(Ah[mt], stA + (uint32_t)ks * 3072 + aLane
                              + (uint32_t)mt * 768);

            const uint32_t bH = stB + (uint32_t)ks * 16384 + bRow;
            // register double-buffered B fragments
            uint32_t Bh[2][4];
            ldsm4t(Bh[0], bH + ((uBase ^ swz) << 4));
#pragma unroll
            for (int j = 0; j < 4; j++) {
                const int cu = j & 1, nx = cu ^ 1;
                if (j < 3) {
                    const uint32_t u = uBase + (uint32_t)(j + 1) * 2;
                    ldsm4t(Bh[nx], bH + ((u ^ swz) << 4));
                }
#pragma unroll
                for (int mt = 0; mt < 2; mt++) {
#pragma unroll
                    for (int nn = 0; nn < 2; nn++) {
                        float* d = acc[mt][j * 2 + nn];
                        mma16816(d, Ah[mt], Bh[cu][nn * 2], Bh[cu][nn * 2 + 1]);
                    }
                }
            }
        }
    }

    // ======== fused epilogue: +bias, LayerNorm(512), *gamma+beta, ReLU ========
    const int g = lane >> 2, t4 = lane & 3;
    float* ps = (float*)(smem + OFF_PS);      // [64 rows][8 nw]
    float* pq = (float*)(smem + OFF_PQ);
    float2* mz = (float2*)(smem + OFF_MZ);    // [64] {mu, rstd}

    float sA[4] = {0.f, 0.f, 0.f, 0.f}, qA[4] = {0.f, 0.f, 0.f, 0.f};
#pragma unroll
    for (int mt = 0; mt < 2; mt++) {
#pragma unroll
        for (int ng = 0; ng < 8; ng++) {
            const int col = nw * 64 + ng * 8 + t4 * 2;
            const float2 bv = *(const float2*)(bias + col);
            acc[mt][ng][0] += bv.x; acc[mt][ng][1] += bv.y;
            acc[mt][ng][2] += bv.x; acc[mt][ng][3] += bv.y;
            sA[mt * 2 + 0] += acc[mt][ng][0] + acc[mt][ng][1];
            qA[mt * 2 + 0] += acc[mt][ng][0] * acc[mt][ng][0]
                            + acc[mt][ng][1] * acc[mt][ng][1];
            sA[mt * 2 + 1] += acc[mt][ng][2] + acc[mt][ng][3];
            qA[mt * 2 + 1] += acc[mt][ng][2] * acc[mt][ng][2]
                            + acc[mt][ng][3] * acc[mt][ng][3];
        }
    }
#pragma unroll
    for (int r4 = 0; r4 < 4; r4++) {
        sA[r4] += __shfl_xor_sync(0xffffffffu, sA[r4], 1);
        qA[r4] += __shfl_xor_sync(0xffffffffu, qA[r4], 1);
        sA[r4] += __shfl_xor_sync(0xffffffffu, sA[r4], 2);
        qA[r4] += __shfl_xor_sync(0xffffffffu, qA[r4], 2);
    }
    if (t4 == 0) {
#pragma unroll
        for (int r4 = 0; r4 < 4; r4++) {
            const int row = mw * 32 + (r4 >> 1) * 16 + (r4 & 1) * 8 + g;
            ps[row * 8 + nw] = sA[r4];
            pq[row * 8 + nw] = qA[r4];
        }
    }
    __syncthreads();
    if (tid < 64) {
        float ss = 0.f, qq = 0.f;
#pragma unroll
        for (int w = 0; w < 8; w++) { ss += ps[tid * 8 + w]; qq += pq[tid * 8 + w]; }
        const float mu  = ss * (1.0f / 512.0f);
        const float var = qq * (1.0f / 512.0f) - mu * mu;
        mz[tid] = make_float2(mu, rsqrtf(var + 1e-5f));
    }
    __syncthreads();

#pragma unroll
    for (int mt = 0; mt < 2; mt++) {
#pragma unroll
        for (int h = 0; h < 2; h++) {
            const int row = mw * 32 + mt * 16 + h * 8 + g;
            const float2 m = mz[row];
#pragma unroll
            for (int ng = 0; ng < 8; ng++) {
                const int col = nw * 64 + ng * 8 + t4 * 2;
                const float2 gv = *(const float2*)(gamma + col);
                const float2 tv = *(const float2*)(beta + col);
                const float v0 = acc[mt][ng][h * 2 + 0];
                const float v1 = acc[mt][ng][h * 2 + 1];
                const float o0 = fmaxf((v0 - m.x) * m.y * gv.x + tv.x, 0.0f);
                const float o1 = fmaxf((v1 - m.x) * m.y * gv.y + tv.y, 0.0f);
                *(float2*)(out + (size_t)(m0 + row) * 512 + col) = make_float2(o0, o1);
            }
        }
    }
}

extern "C" void kernel_launch(void* const* d_in, const int* in_sizes, int n_in,
                              void* d_out, int out_size)
{
    // metadata order: embeddings, W_proj, b_proj, W_enc, b_enc, ln_gamma, ln_beta
    const float* emb   = (const float*)d_in[0];
    const float* W_enc = (const float*)d_in[3];
    const float* b_enc = (const float*)d_in[4];
    const float* gam   = (const float*)d_in[5];
    const float* bet   = (const float*)d_in[6];
    float* out = (float*)d_out;

    prep_b_kernel<<<128, 256>>>(W_enc);

    cudaFuncSetAttribute(gemm_ln_kernel,
                         cudaFuncAttributeMaxDynamicSharedMemorySize, SMEM_TOTAL);
    gemm_ln_kernel<<<16384 / MTILE, THREADS, SMEM_TOTAL>>>(emb, b_enc, gam, bet, out);
}